// round 1
// baseline (speedup 1.0000x reference)
#include <cuda_runtime.h>
#include <cstdint>

#define N_NODES_C 100000
#define HEADS 4
#define OUT_CH 32
#define IN_CH 128
#define HC 128            // HEADS*OUT_CH
#define EPS_F 1e-8f

// ---------------- device scratch (no allocs allowed) ----------------
__device__ float g_h[(size_t)N_NODES_C * HC];          // projected features [N,128]  (51.2MB)
__device__ float g_at[N_NODES_C * HEADS];              // alpha_target
__device__ float g_as[N_NODES_C * HEADS];              // alpha_source
__device__ float g_den[N_NODES_C * HEADS];             // softmax denominators
__device__ unsigned int g_maxbits;                     // ordered-encoded global max of e
__device__ int g_is64;                                 // edge index dtype flag

// ordered float <-> uint mapping for atomicMax on floats
__device__ __forceinline__ unsigned int f2o(float f) {
    unsigned int b = __float_as_uint(f);
    return (b & 0x80000000u) ? ~b : (b | 0x80000000u);
}
__device__ __forceinline__ float o2f(unsigned int u) {
    unsigned int b = (u & 0x80000000u) ? (u ^ 0x80000000u) : ~u;
    return __uint_as_float(b);
}

__device__ __forceinline__ int ldidx(const void* p, long long i, int is64) {
    return is64 ? (int)((const long long*)p)[i] : ((const int*)p)[i];
}

// ---------------- init: dtype detection + max reset ----------------
__global__ void init_kernel(const void* __restrict__ idx, int nscan, int nnodes) {
    __shared__ int bad;
    if (threadIdx.x == 0) bad = 0;
    __syncthreads();
    const long long* p = (const long long*)idx;
    int ok = 1;
    for (int i = threadIdx.x; i < nscan; i += blockDim.x) {
        long long v = p[i];
        if (v < 0 || v >= (long long)nnodes) ok = 0;
    }
    if (!ok) atomicExch(&bad, 1);
    __syncthreads();
    if (threadIdx.x == 0) {
        g_is64 = bad ? 0 : 1;   // all in-range as int64 -> really int64
        g_maxbits = 0u;
    }
}

// ---------------- GEMM: h = X @ W^T + b   (M x 128) ----------------
// BM=128, BN=128(full), BK=16, 16x16 threads, 8x8 per-thread tile
__global__ __launch_bounds__(256) void gemm_kernel(
    const float* __restrict__ X, const float* __restrict__ W,
    const float* __restrict__ bias, int M)
{
    __shared__ float As[16][128];
    __shared__ float Bs[16][128];
    const int tid = threadIdx.x;
    const int tx = tid & 15;        // col group
    const int ty = tid >> 4;        // row group
    const int rowBase = blockIdx.x * 128;

    float acc[8][8];
#pragma unroll
    for (int i = 0; i < 8; i++)
#pragma unroll
        for (int j = 0; j < 8; j++) acc[i][j] = 0.f;

    for (int k0 = 0; k0 < IN_CH; k0 += 16) {
        // cooperative load: 128x16 of X and 128x16 of W (as B^T)
#pragma unroll
        for (int it = 0; it < 2; it++) {
            int l = tid + it * 256;         // 0..511
            int r = l >> 2;                 // 0..127
            int kq = (l & 3) * 4;           // float4 offset inside the 16-wide K slab
            int grow = rowBase + r;
            float4 va = make_float4(0.f, 0.f, 0.f, 0.f);
            if (grow < M) va = *(const float4*)(X + (size_t)grow * IN_CH + k0 + kq);
            As[kq + 0][r] = va.x; As[kq + 1][r] = va.y;
            As[kq + 2][r] = va.z; As[kq + 3][r] = va.w;
            float4 vb = *(const float4*)(W + (size_t)r * IN_CH + k0 + kq);
            Bs[kq + 0][r] = vb.x; Bs[kq + 1][r] = vb.y;
            Bs[kq + 2][r] = vb.z; Bs[kq + 3][r] = vb.w;
        }
        __syncthreads();
#pragma unroll
        for (int kk = 0; kk < 16; kk++) {
            float a[8], b[8];
#pragma unroll
            for (int i = 0; i < 8; i++) a[i] = As[kk][ty * 8 + i];
#pragma unroll
            for (int j = 0; j < 8; j++) b[j] = Bs[kk][tx * 8 + j];
#pragma unroll
            for (int i = 0; i < 8; i++)
#pragma unroll
                for (int j = 0; j < 8; j++) acc[i][j] += a[i] * b[j];
        }
        __syncthreads();
    }

    const float4 b0 = *(const float4*)(bias + tx * 8);
    const float4 b1 = *(const float4*)(bias + tx * 8 + 4);
#pragma unroll
    for (int i = 0; i < 8; i++) {
        int r = rowBase + ty * 8 + i;
        if (r < M) {
            float4 o0 = make_float4(acc[i][0] + b0.x, acc[i][1] + b0.y,
                                    acc[i][2] + b0.z, acc[i][3] + b0.w);
            float4 o1 = make_float4(acc[i][4] + b1.x, acc[i][5] + b1.y,
                                    acc[i][6] + b1.z, acc[i][7] + b1.w);
            *(float4*)(g_h + (size_t)r * HC + tx * 8) = o0;
            *(float4*)(g_h + (size_t)r * HC + tx * 8 + 4) = o1;
        }
    }
}

// ---------------- per-node attention dot products ----------------
// 2 nodes per 256-thread block; warp w handles head w of its node
__global__ __launch_bounds__(256) void alpha_kernel(const float* __restrict__ att, int M) {
    int node = blockIdx.x * 2 + (threadIdx.x >> 7);
    if (node >= M) return;
    int c = threadIdx.x & 127;
    int head = c >> 5, cc = c & 31;
    float v = g_h[(size_t)node * HC + c];
    float pt = v * att[head * 64 + cc];
    float ps = v * att[head * 64 + 32 + cc];
#pragma unroll
    for (int o = 16; o; o >>= 1) {
        pt += __shfl_down_sync(0xffffffffu, pt, o);
        ps += __shfl_down_sync(0xffffffffu, ps, o);
    }
    if (cc == 0) {
        g_at[node * HEADS + head] = pt;
        g_as[node * HEADS + head] = ps;
    }
}

// ---------------- global max of edge logits ----------------
__global__ __launch_bounds__(256) void edgemax_kernel(const void* __restrict__ idx, int E) {
    int i = blockIdx.x * blockDim.x + threadIdx.x;
    int is64 = g_is64;
    float m = -3.4e38f;
    if (i < E) {
        int s = ldidx(idx, i, is64);
        int t = ldidx(idx, (long long)E + i, is64);
#pragma unroll
        for (int h = 0; h < HEADS; h++)
            m = fmaxf(m, g_at[t * HEADS + h] + g_as[s * HEADS + h]);
    }
    unsigned int u = f2o(m);
#pragma unroll
    for (int o = 16; o; o >>= 1)
        u = max(u, __shfl_down_sync(0xffffffffu, u, o));
    __shared__ unsigned int sm[8];
    int lane = threadIdx.x & 31, warp = threadIdx.x >> 5;
    if (lane == 0) sm[warp] = u;
    __syncthreads();
    if (warp == 0) {
        u = (lane < 8) ? sm[lane] : 0u;
#pragma unroll
        for (int o = 4; o; o >>= 1)
            u = max(u, __shfl_down_sync(0xffffffffu, u, o));
        if (lane == 0) atomicMax(&g_maxbits, u);
    }
}

// ---------------- softmax denominators (+ zero them first) ----------------
__global__ __launch_bounds__(256) void zero_den_kernel(int M) {
    int i = blockIdx.x * blockDim.x + threadIdx.x;
    if (i < M * HEADS) g_den[i] = 0.f;
}

__global__ __launch_bounds__(256) void denom_kernel(const void* __restrict__ idx, int E) {
    int i = blockIdx.x * blockDim.x + threadIdx.x;
    if (i >= E) return;
    int is64 = g_is64;
    int s = ldidx(idx, i, is64);
    int t = ldidx(idx, (long long)E + i, is64);
    float gmax = o2f(g_maxbits);
#pragma unroll
    for (int h = 0; h < HEADS; h++) {
        float e = g_at[t * HEADS + h] + g_as[s * HEADS + h];
        float d = e - gmax;
        float lr = d > 0.f ? d : 0.01f * d;
        atomicAdd(&g_den[t * HEADS + h], __expf(lr));
    }
}

// ---------------- weighted aggregation (one warp per edge) ----------------
__global__ __launch_bounds__(256) void agg_kernel(const void* __restrict__ idx, int E,
                                                  float* __restrict__ out) {
    long long gw = ((long long)blockIdx.x * blockDim.x + threadIdx.x) >> 5;
    if (gw >= E) return;
    int lane = threadIdx.x & 31;
    int is64 = g_is64;
    int s = ldidx(idx, gw, is64);
    int t = ldidx(idx, (long long)E + gw, is64);
    float gmax = o2f(g_maxbits);
    float w[HEADS];
#pragma unroll
    for (int h = 0; h < HEADS; h++) {
        float e = g_at[t * HEADS + h] + g_as[s * HEADS + h];
        float d = e - gmax;
        float lr = d > 0.f ? d : 0.01f * d;
        float a = __expf(lr);
        w[h] = 0.25f * a / (g_den[t * HEADS + h] + EPS_F);
    }
    const float* hs = g_h + (size_t)s * HC;
    float val = w[0] * hs[lane] + w[1] * hs[32 + lane]
              + w[2] * hs[64 + lane] + w[3] * hs[96 + lane];
    atomicAdd(&out[(size_t)t * OUT_CH + lane], val);
}

// ---------------- launch ----------------
extern "C" void kernel_launch(void* const* d_in, const int* in_sizes, int n_in,
                              void* d_out, int out_size) {
    const float* X    = (const float*)d_in[0];
    const void*  eidx = d_in[1];
    const float* W    = (const float*)d_in[2];
    const float* bias = (const float*)d_in[3];
    const float* att  = (const float*)d_in[4];
    float* out = (float*)d_out;

    int M = in_sizes[0] / IN_CH;          // nodes
    int E = in_sizes[1] / 2;              // edges (element count is dtype-agnostic here)

    int nscan = E < 2048 ? E : 2048;
    init_kernel<<<1, 256>>>(eidx, nscan, M);

    cudaMemsetAsync(d_out, 0, (size_t)out_size * sizeof(float));
    zero_den_kernel<<<(M * HEADS + 255) / 256, 256>>>(M);

    gemm_kernel<<<(M + 127) / 128, 256>>>(X, W, bias, M);
    alpha_kernel<<<(M + 1) / 2, 256>>>(att, M);
    edgemax_kernel<<<(E + 255) / 256, 256>>>(eidx, E);
    denom_kernel<<<(E + 255) / 256, 256>>>(eidx, E);

    long long aggThreads = (long long)E * 32;
    agg_kernel<<<(unsigned)((aggThreads + 255) / 256), 256>>>(eidx, E, out);
}

// round 3
// speedup vs baseline: 1.2921x; 1.2921x over previous
#include <cuda_runtime.h>
#include <cuda_bf16.h>
#include <cstdint>

#define N_NODES_C 100000
#define HEADS 4
#define OUT_CH 32
#define IN_CH 128
#define HC 128            // HEADS*OUT_CH
#define EPS_F 1e-8f
#define TILE_M 128
#define LDA 136           // padded row length (bf16 elems) = 128 + 8

// ---------------- device scratch (no allocs allowed) ----------------
__device__ __align__(16) float g_h[(size_t)N_NODES_C * HC];   // projected features [N,128]
__device__ __align__(16) float g_at[N_NODES_C * HEADS];       // alpha_target
__device__ __align__(16) float g_as[N_NODES_C * HEADS];       // alpha_source
__device__ float g_den[N_NODES_C * HEADS];                    // softmax denominators
__device__ unsigned int g_maxbits;                            // ordered-encoded global max
__device__ int g_is64;                                        // edge index dtype flag
__device__ __align__(16) unsigned short g_Whi[HC * LDA];      // W bf16 hi, padded [n][k]
__device__ __align__(16) unsigned short g_Wlo[HC * LDA];      // W bf16 lo, padded [n][k]

// ordered float <-> uint mapping for atomicMax on floats
__device__ __forceinline__ unsigned int f2o(float f) {
    unsigned int b = __float_as_uint(f);
    return (b & 0x80000000u) ? ~b : (b | 0x80000000u);
}
__device__ __forceinline__ float o2f(unsigned int u) {
    unsigned int b = (u & 0x80000000u) ? (u ^ 0x80000000u) : ~u;
    return __uint_as_float(b);
}
__device__ __forceinline__ int ldidx(const void* p, long long i, int is64) {
    return is64 ? (int)((const long long*)p)[i] : ((const int*)p)[i];
}

__device__ __forceinline__ uint32_t smem_u32(const void* p) {
    uint32_t a;
    asm("{ .reg .u64 t; cvta.to.shared.u64 t, %1; cvt.u32.u64 %0, t; }" : "=r"(a) : "l"(p));
    return a;
}
__device__ __forceinline__ void ldm_x4(uint32_t* r, uint32_t addr) {
    asm volatile("ldmatrix.sync.aligned.m8n8.x4.shared.b16 {%0,%1,%2,%3}, [%4];"
                 : "=r"(r[0]), "=r"(r[1]), "=r"(r[2]), "=r"(r[3]) : "r"(addr));
}
__device__ __forceinline__ void mma_bf16(float* d, const uint32_t* a, const uint32_t* b) {
    asm volatile(
        "mma.sync.aligned.m16n8k16.row.col.f32.bf16.bf16.f32 "
        "{%0,%1,%2,%3}, {%4,%5,%6,%7}, {%8,%9}, {%0,%1,%2,%3};"
        : "+f"(d[0]), "+f"(d[1]), "+f"(d[2]), "+f"(d[3])
        : "r"(a[0]), "r"(a[1]), "r"(a[2]), "r"(a[3]), "r"(b[0]), "r"(b[1]));
}

// SMEM layout (bytes)
#define SM_BIAS 0
#define SM_ATT  512
#define SM_AHI  1536
#define SM_TILE_BYTES (128 * LDA * 2)     // 34816
#define SM_ALO  (SM_AHI + SM_TILE_BYTES)
#define SM_BHI  (SM_ALO + SM_TILE_BYTES)
#define SM_BLO  (SM_BHI + SM_TILE_BYTES)
#define SM_TOTAL (SM_BLO + SM_TILE_BYTES) // 140800

// ---------------- init: dtype detection + max reset ----------------
__global__ void init_kernel(const void* __restrict__ idx, int nscan, int nnodes) {
    __shared__ int bad;
    if (threadIdx.x == 0) bad = 0;
    __syncthreads();
    const long long* p = (const long long*)idx;
    int ok = 1;
    for (int i = threadIdx.x; i < nscan; i += blockDim.x) {
        long long v = p[i];
        if (v < 0 || v >= (long long)nnodes) ok = 0;
    }
    if (!ok) atomicExch(&bad, 1);
    __syncthreads();
    if (threadIdx.x == 0) {
        g_is64 = bad ? 0 : 1;
        g_maxbits = 0u;
    }
}

// ---------------- W -> bf16 hi/lo, padded row-major [n][k] ----------------
__global__ void prep_w_kernel(const float* __restrict__ W) {
    for (int idx = blockIdx.x * blockDim.x + threadIdx.x; idx < HC * IN_CH;
         idx += blockDim.x * gridDim.x) {
        int n = idx >> 7;        // output channel
        int k = idx & 127;       // input channel
        float w = W[idx];
        __nv_bfloat16 hi = __float2bfloat16(w);
        float rem = w - __bfloat162float(hi);
        __nv_bfloat16 lo = __float2bfloat16(rem);
        g_Whi[n * LDA + k] = __bfloat16_as_ushort(hi);
        g_Wlo[n * LDA + k] = __bfloat16_as_ushort(lo);
    }
}

// ---------------- mma.sync GEMM + fused alpha epilogue ----------------
// 128x128 tile per CTA; 8 warps in 4x2 (row x col); warp tile 32x64.
// D = (Xhi+Xlo)(Whi+Wlo)^T via 3 accumulated bf16 products.
__global__ void __launch_bounds__(256, 1)
gat_gemm_kernel(const float* __restrict__ X, const float* __restrict__ bias,
                const float* __restrict__ att, int M) {
    extern __shared__ char smem[];
    const int tid = threadIdx.x, lane = tid & 31, wid = tid >> 5;
    const int rowBase = blockIdx.x * TILE_M;

    if (tid < 128) ((float*)(smem + SM_BIAS))[tid] = bias[tid];
    ((float*)(smem + SM_ATT))[tid] = att[tid];   // 256 floats

    // W tiles: raw copies of pre-split padded bf16 (34816 B each = 2176 float4)
    {
        const float4* wh = (const float4*)g_Whi;
        const float4* wl = (const float4*)g_Wlo;
        float4* dh = (float4*)(smem + SM_BHI);
        float4* dl = (float4*)(smem + SM_BLO);
        for (int g = tid; g < SM_TILE_BYTES / 16; g += 256) {
            dh[g] = wh[g];
            dl[g] = wl[g];
        }
    }
    // A tile: load fp32 X, split into bf16 hi/lo, padded layout
#pragma unroll
    for (int it = 0; it < 16; it++) {
        int g = tid + it * 256;        // 0..4095
        int r = g >> 5;
        int c4 = (g & 31) * 4;
        int grow = rowBase + r;
        float4 v = make_float4(0.f, 0.f, 0.f, 0.f);
        if (grow < M) v = *(const float4*)(X + (size_t)grow * IN_CH + c4);
        __nv_bfloat16 h0 = __float2bfloat16(v.x);
        __nv_bfloat16 h1 = __float2bfloat16(v.y);
        __nv_bfloat16 h2 = __float2bfloat16(v.z);
        __nv_bfloat16 h3 = __float2bfloat16(v.w);
        __nv_bfloat16 l0 = __float2bfloat16(v.x - __bfloat162float(h0));
        __nv_bfloat16 l1 = __float2bfloat16(v.y - __bfloat162float(h1));
        __nv_bfloat16 l2 = __float2bfloat16(v.z - __bfloat162float(h2));
        __nv_bfloat16 l3 = __float2bfloat16(v.w - __bfloat162float(h3));
        uint32_t hiA = ((uint32_t)__bfloat16_as_ushort(h1) << 16) | __bfloat16_as_ushort(h0);
        uint32_t hiB = ((uint32_t)__bfloat16_as_ushort(h3) << 16) | __bfloat16_as_ushort(h2);
        uint32_t loA = ((uint32_t)__bfloat16_as_ushort(l1) << 16) | __bfloat16_as_ushort(l0);
        uint32_t loB = ((uint32_t)__bfloat16_as_ushort(l3) << 16) | __bfloat16_as_ushort(l2);
        size_t off = ((size_t)r * LDA + c4) * 2;
        *(uint2*)(smem + SM_AHI + off) = make_uint2(hiA, hiB);
        *(uint2*)(smem + SM_ALO + off) = make_uint2(loA, loB);
    }
    __syncthreads();

    const int wr = wid & 3, wc = wid >> 2;
    const int mrow = wr * 32;             // warp row base in tile
    const int ncol = wc * 64;             // warp col base (W row base)

    float acc[2][8][4];
#pragma unroll
    for (int mt = 0; mt < 2; mt++)
#pragma unroll
        for (int nt = 0; nt < 8; nt++)
#pragma unroll
            for (int i = 0; i < 4; i++) acc[mt][nt][i] = 0.f;

    // precomputed lane address components
    const int a_row = (lane & 15);                 // within 16-row mtile
    const int a_koff = (lane >> 4) * 8;            // 0 or 8
    const int b_nr = (lane & 7) + ((lane >> 4) & 1) * 8;   // n within 16-row pair
    const int b_koff = ((lane >> 3) & 1) * 8;      // 0 or 8

#pragma unroll
    for (int p = 0; p < 3; p++) {
        const char* Ab = smem + (p == 2 ? SM_ALO : SM_AHI);
        const char* Bb = smem + (p == 1 ? SM_BLO : SM_BHI);
#pragma unroll
        for (int ks = 0; ks < 8; ks++) {
            const int k0 = ks * 16;
            uint32_t a[2][4];
#pragma unroll
            for (int mt = 0; mt < 2; mt++) {
                uint32_t ad = smem_u32(Ab + ((size_t)(mrow + mt * 16 + a_row) * LDA
                                             + k0 + a_koff) * 2);
                ldm_x4(a[mt], ad);
            }
            uint32_t b[4][4];
#pragma unroll
            for (int np = 0; np < 4; np++) {
                uint32_t bd = smem_u32(Bb + ((size_t)(ncol + np * 16 + b_nr) * LDA
                                             + k0 + b_koff) * 2);
                ldm_x4(b[np], bd);
            }
#pragma unroll
            for (int mt = 0; mt < 2; mt++)
#pragma unroll
                for (int nt = 0; nt < 8; nt++)
                    mma_bf16(acc[mt][nt], a[mt], &b[nt >> 1][(nt & 1) * 2]);
        }
    }

    // ---------------- epilogue: bias, store g_h, fused alpha dots ----------------
    const float* s_bias = (const float*)(smem + SM_BIAS);
    const float* s_att = (const float*)(smem + SM_ATT);
    const int q = lane & 3, rg = lane >> 2;

#pragma unroll
    for (int mt = 0; mt < 2; mt++) {
#pragma unroll
        for (int hh = 0; hh < 2; hh++) {
            const int r = mrow + mt * 16 + rg + hh * 8;
            const int grow = rowBase + r;
            const bool valid = grow < M;
            float pt0 = 0.f, ps0 = 0.f, pt1 = 0.f, ps1 = 0.f;
#pragma unroll
            for (int nt = 0; nt < 8; nt++) {
                const int col = ncol + nt * 8 + 2 * q;
                float v0 = acc[mt][nt][hh * 2 + 0] + s_bias[col];
                float v1 = acc[mt][nt][hh * 2 + 1] + s_bias[col + 1];
                if (valid)
                    *(float2*)(g_h + (size_t)grow * HC + col) = make_float2(v0, v1);
                const int head = wc * 2 + (nt >> 2);
                const int c0 = col & 31;
                const float at0 = s_att[head * 64 + c0], at1 = s_att[head * 64 + c0 + 1];
                const float as0 = s_att[head * 64 + 32 + c0], as1 = s_att[head * 64 + 33 + c0];
                if (nt < 4) { pt0 += v0 * at0 + v1 * at1; ps0 += v0 * as0 + v1 * as1; }
                else        { pt1 += v0 * at0 + v1 * at1; ps1 += v0 * as0 + v1 * as1; }
            }
            // quad reduce (lanes sharing a row are q=0..3)
#pragma unroll
            for (int o = 1; o <= 2; o <<= 1) {
                pt0 += __shfl_xor_sync(0xffffffffu, pt0, o);
                ps0 += __shfl_xor_sync(0xffffffffu, ps0, o);
                pt1 += __shfl_xor_sync(0xffffffffu, pt1, o);
                ps1 += __shfl_xor_sync(0xffffffffu, ps1, o);
            }
            if (q == 0 && valid) {
                const int h0 = wc * 2;
                g_at[(size_t)grow * HEADS + h0] = pt0;
                g_at[(size_t)grow * HEADS + h0 + 1] = pt1;
                g_as[(size_t)grow * HEADS + h0] = ps0;
                g_as[(size_t)grow * HEADS + h0 + 1] = ps1;
            }
        }
    }
}

// ---------------- global max of edge logits ----------------
__global__ __launch_bounds__(256) void edgemax_kernel(const void* __restrict__ idx, int E) {
    int i = blockIdx.x * blockDim.x + threadIdx.x;
    int is64 = g_is64;
    float m = -3.4e38f;
    if (i < E) {
        int s = ldidx(idx, i, is64);
        int t = ldidx(idx, (long long)E + i, is64);
#pragma unroll
        for (int h = 0; h < HEADS; h++)
            m = fmaxf(m, g_at[t * HEADS + h] + g_as[s * HEADS + h]);
    }
    unsigned int u = f2o(m);
#pragma unroll
    for (int o = 16; o; o >>= 1)
        u = max(u, __shfl_down_sync(0xffffffffu, u, o));
    __shared__ unsigned int sm[8];
    int lane = threadIdx.x & 31, warp = threadIdx.x >> 5;
    if (lane == 0) sm[warp] = u;
    __syncthreads();
    if (warp == 0) {
        u = (lane < 8) ? sm[lane] : 0u;
#pragma unroll
        for (int o = 4; o; o >>= 1)
            u = max(u, __shfl_down_sync(0xffffffffu, u, o));
        if (lane == 0) atomicMax(&g_maxbits, u);
    }
}

// ---------------- softmax denominators (+ zero them first) ----------------
__global__ __launch_bounds__(256) void zero_den_kernel(int M) {
    int i = blockIdx.x * blockDim.x + threadIdx.x;
    if (i < M * HEADS) g_den[i] = 0.f;
}

__global__ __launch_bounds__(256) void denom_kernel(const void* __restrict__ idx, int E) {
    int i = blockIdx.x * blockDim.x + threadIdx.x;
    if (i >= E) return;
    int is64 = g_is64;
    int s = ldidx(idx, i, is64);
    int t = ldidx(idx, (long long)E + i, is64);
    float gmax = o2f(g_maxbits);
#pragma unroll
    for (int h = 0; h < HEADS; h++) {
        float e = g_at[t * HEADS + h] + g_as[s * HEADS + h];
        float d = e - gmax;
        float lr = d > 0.f ? d : 0.01f * d;
        atomicAdd(&g_den[t * HEADS + h], __expf(lr));
    }
}

// ---------------- weighted aggregation (one warp per edge) ----------------
__global__ __launch_bounds__(256) void agg_kernel(const void* __restrict__ idx, int E,
                                                  float* __restrict__ out) {
    long long gw = ((long long)blockIdx.x * blockDim.x + threadIdx.x) >> 5;
    if (gw >= E) return;
    int lane = threadIdx.x & 31;
    int is64 = g_is64;
    int s = ldidx(idx, gw, is64);
    int t = ldidx(idx, (long long)E + gw, is64);
    float gmax = o2f(g_maxbits);
    float w[HEADS];
#pragma unroll
    for (int h = 0; h < HEADS; h++) {
        float e = g_at[t * HEADS + h] + g_as[s * HEADS + h];
        float d = e - gmax;
        float lr = d > 0.f ? d : 0.01f * d;
        float a = __expf(lr);
        w[h] = 0.25f * a / (g_den[t * HEADS + h] + EPS_F);
    }
    const float* hs = g_h + (size_t)s * HC;
    float val = w[0] * hs[lane] + w[1] * hs[32 + lane]
              + w[2] * hs[64 + lane] + w[3] * hs[96 + lane];
    atomicAdd(&out[(size_t)t * OUT_CH + lane], val);
}

// ---------------- launch ----------------
extern "C" void kernel_launch(void* const* d_in, const int* in_sizes, int n_in,
                              void* d_out, int out_size) {
    const float* X    = (const float*)d_in[0];
    const void*  eidx = d_in[1];
    const float* W    = (const float*)d_in[2];
    const float* bias = (const float*)d_in[3];
    const float* att  = (const float*)d_in[4];
    float* out = (float*)d_out;

    int M = in_sizes[0] / IN_CH;          // nodes
    int E = in_sizes[1] / 2;              // edges

    cudaFuncSetAttribute(gat_gemm_kernel,
                         cudaFuncAttributeMaxDynamicSharedMemorySize, SM_TOTAL);

    int nscan = E < 2048 ? E : 2048;
    init_kernel<<<1, 256>>>(eidx, nscan, M);
    prep_w_kernel<<<32, 256>>>(W);

    cudaMemsetAsync(d_out, 0, (size_t)out_size * sizeof(float));
    zero_den_kernel<<<(M * HEADS + 255) / 256, 256>>>(M);

    gat_gemm_kernel<<<(M + TILE_M - 1) / TILE_M, 256, SM_TOTAL>>>(X, bias, att, M);

    edgemax_kernel<<<(E + 255) / 256, 256>>>(eidx, E);
    denom_kernel<<<(E + 255) / 256, 256>>>(eidx, E);

    long long aggThreads = (long long)E * 32;
    agg_kernel<<<(unsigned)((aggThreads + 255) / 256), 256>>>(eidx, E, out);
}

// round 4
// speedup vs baseline: 2.3739x; 1.8373x over previous
#include <cuda_runtime.h>
#include <cuda_bf16.h>
#include <cstdint>

#define N_NODES_C 100000
#define N_EDGES_C 800000
#define HEADS 4
#define OUT_CH 32
#define IN_CH 128
#define HC 128            // HEADS*OUT_CH
#define EPS_F 1e-8f
#define TILE_M 128
#define LDA 136           // padded row length (bf16 elems) = 128 + 8

// ---------------- device scratch (no allocs allowed) ----------------
__device__ __align__(16) float g_h[(size_t)N_NODES_C * HC];   // projected features [N,128]
__device__ __align__(16) float g_at[N_NODES_C * HEADS];       // alpha_target
__device__ __align__(16) float g_as[N_NODES_C * HEADS];       // alpha_source
__device__ __align__(16) float g_den[N_NODES_C * HEADS];      // softmax denominators
__device__ __align__(16) int2  g_edges[N_EDGES_C];            // decoded (s,t)
__device__ __align__(16) float4 g_e4[N_EDGES_C];              // per-edge logits -> weights
__device__ unsigned int g_maxbits;                            // ordered-encoded global max
__device__ int g_is64;                                        // edge index dtype flag
__device__ __align__(16) unsigned short g_Whi[HC * LDA];      // W bf16 hi, padded [n][k]
__device__ __align__(16) unsigned short g_Wlo[HC * LDA];      // W bf16 lo, padded [n][k]

// ordered float <-> uint mapping for atomicMax on floats
__device__ __forceinline__ unsigned int f2o(float f) {
    unsigned int b = __float_as_uint(f);
    return (b & 0x80000000u) ? ~b : (b | 0x80000000u);
}
__device__ __forceinline__ float o2f(unsigned int u) {
    unsigned int b = (u & 0x80000000u) ? (u ^ 0x80000000u) : ~u;
    return __uint_as_float(b);
}
__device__ __forceinline__ int ldidx(const void* p, long long i, int is64) {
    return is64 ? (int)((const long long*)p)[i] : ((const int*)p)[i];
}
__device__ __forceinline__ void red_v4(float* ptr, float4 v) {
    asm volatile("red.global.add.v4.f32 [%0], {%1,%2,%3,%4};"
                 :: "l"(ptr), "f"(v.x), "f"(v.y), "f"(v.z), "f"(v.w) : "memory");
}

__device__ __forceinline__ uint32_t smem_u32(const void* p) {
    uint32_t a;
    asm("{ .reg .u64 t; cvta.to.shared.u64 t, %1; cvt.u32.u64 %0, t; }" : "=r"(a) : "l"(p));
    return a;
}
__device__ __forceinline__ void ldm_x4(uint32_t* r, uint32_t addr) {
    asm volatile("ldmatrix.sync.aligned.m8n8.x4.shared.b16 {%0,%1,%2,%3}, [%4];"
                 : "=r"(r[0]), "=r"(r[1]), "=r"(r[2]), "=r"(r[3]) : "r"(addr));
}
__device__ __forceinline__ void mma_bf16(float* d, const uint32_t* a, const uint32_t* b) {
    asm volatile(
        "mma.sync.aligned.m16n8k16.row.col.f32.bf16.bf16.f32 "
        "{%0,%1,%2,%3}, {%4,%5,%6,%7}, {%8,%9}, {%0,%1,%2,%3};"
        : "+f"(d[0]), "+f"(d[1]), "+f"(d[2]), "+f"(d[3])
        : "r"(a[0]), "r"(a[1]), "r"(a[2]), "r"(a[3]), "r"(b[0]), "r"(b[1]));
}

// SMEM layout (bytes)
#define SM_BIAS 0
#define SM_ATT  512
#define SM_AHI  1536
#define SM_TILE_BYTES (128 * LDA * 2)     // 34816
#define SM_ALO  (SM_AHI + SM_TILE_BYTES)
#define SM_BHI  (SM_ALO + SM_TILE_BYTES)
#define SM_BLO  (SM_BHI + SM_TILE_BYTES)
#define SM_TOTAL (SM_BLO + SM_TILE_BYTES) // 140800

// ---------------- init: dtype detection + max reset ----------------
__global__ void init_kernel(const void* __restrict__ idx, int nscan, int nnodes) {
    __shared__ int bad;
    if (threadIdx.x == 0) bad = 0;
    __syncthreads();
    const long long* p = (const long long*)idx;
    int ok = 1;
    for (int i = threadIdx.x; i < nscan; i += blockDim.x) {
        long long v = p[i];
        if (v < 0 || v >= (long long)nnodes) ok = 0;
    }
    if (!ok) atomicExch(&bad, 1);
    __syncthreads();
    if (threadIdx.x == 0) {
        g_is64 = bad ? 0 : 1;
        g_maxbits = 0u;
    }
}

// ---------------- W -> bf16 hi/lo, padded row-major [n][k] ----------------
__global__ void prep_w_kernel(const float* __restrict__ W) {
    for (int idx = blockIdx.x * blockDim.x + threadIdx.x; idx < HC * IN_CH;
         idx += blockDim.x * gridDim.x) {
        int n = idx >> 7;
        int k = idx & 127;
        float w = W[idx];
        __nv_bfloat16 hi = __float2bfloat16(w);
        float rem = w - __bfloat162float(hi);
        __nv_bfloat16 lo = __float2bfloat16(rem);
        g_Whi[n * LDA + k] = __bfloat16_as_ushort(hi);
        g_Wlo[n * LDA + k] = __bfloat16_as_ushort(lo);
    }
}

// ---------------- mma.sync GEMM + fused alpha epilogue ----------------
__global__ void __launch_bounds__(256, 1)
gat_gemm_kernel(const float* __restrict__ X, const float* __restrict__ bias,
                const float* __restrict__ att, int M) {
    extern __shared__ char smem[];
    const int tid = threadIdx.x, lane = tid & 31, wid = tid >> 5;
    const int rowBase = blockIdx.x * TILE_M;

    if (tid < 128) ((float*)(smem + SM_BIAS))[tid] = bias[tid];
    ((float*)(smem + SM_ATT))[tid] = att[tid];

    {
        const float4* wh = (const float4*)g_Whi;
        const float4* wl = (const float4*)g_Wlo;
        float4* dh = (float4*)(smem + SM_BHI);
        float4* dl = (float4*)(smem + SM_BLO);
        for (int g = tid; g < SM_TILE_BYTES / 16; g += 256) {
            dh[g] = wh[g];
            dl[g] = wl[g];
        }
    }
#pragma unroll
    for (int it = 0; it < 16; it++) {
        int g = tid + it * 256;
        int r = g >> 5;
        int c4 = (g & 31) * 4;
        int grow = rowBase + r;
        float4 v = make_float4(0.f, 0.f, 0.f, 0.f);
        if (grow < M) v = *(const float4*)(X + (size_t)grow * IN_CH + c4);
        __nv_bfloat16 h0 = __float2bfloat16(v.x);
        __nv_bfloat16 h1 = __float2bfloat16(v.y);
        __nv_bfloat16 h2 = __float2bfloat16(v.z);
        __nv_bfloat16 h3 = __float2bfloat16(v.w);
        __nv_bfloat16 l0 = __float2bfloat16(v.x - __bfloat162float(h0));
        __nv_bfloat16 l1 = __float2bfloat16(v.y - __bfloat162float(h1));
        __nv_bfloat16 l2 = __float2bfloat16(v.z - __bfloat162float(h2));
        __nv_bfloat16 l3 = __float2bfloat16(v.w - __bfloat162float(h3));
        uint32_t hiA = ((uint32_t)__bfloat16_as_ushort(h1) << 16) | __bfloat16_as_ushort(h0);
        uint32_t hiB = ((uint32_t)__bfloat16_as_ushort(h3) << 16) | __bfloat16_as_ushort(h2);
        uint32_t loA = ((uint32_t)__bfloat16_as_ushort(l1) << 16) | __bfloat16_as_ushort(l0);
        uint32_t loB = ((uint32_t)__bfloat16_as_ushort(l3) << 16) | __bfloat16_as_ushort(l2);
        size_t off = ((size_t)r * LDA + c4) * 2;
        *(uint2*)(smem + SM_AHI + off) = make_uint2(hiA, hiB);
        *(uint2*)(smem + SM_ALO + off) = make_uint2(loA, loB);
    }
    __syncthreads();

    const int wr = wid & 3, wc = wid >> 2;
    const int mrow = wr * 32;
    const int ncol = wc * 64;

    float acc[2][8][4];
#pragma unroll
    for (int mt = 0; mt < 2; mt++)
#pragma unroll
        for (int nt = 0; nt < 8; nt++)
#pragma unroll
            for (int i = 0; i < 4; i++) acc[mt][nt][i] = 0.f;

    const int a_row = (lane & 15);
    const int a_koff = (lane >> 4) * 8;
    const int b_nr = (lane & 7) + ((lane >> 4) & 1) * 8;
    const int b_koff = ((lane >> 3) & 1) * 8;

#pragma unroll
    for (int p = 0; p < 3; p++) {
        const char* Ab = smem + (p == 2 ? SM_ALO : SM_AHI);
        const char* Bb = smem + (p == 1 ? SM_BLO : SM_BHI);
#pragma unroll
        for (int ks = 0; ks < 8; ks++) {
            const int k0 = ks * 16;
            uint32_t a[2][4];
#pragma unroll
            for (int mt = 0; mt < 2; mt++) {
                uint32_t ad = smem_u32(Ab + ((size_t)(mrow + mt * 16 + a_row) * LDA
                                             + k0 + a_koff) * 2);
                ldm_x4(a[mt], ad);
            }
            uint32_t b[4][4];
#pragma unroll
            for (int np = 0; np < 4; np++) {
                uint32_t bd = smem_u32(Bb + ((size_t)(ncol + np * 16 + b_nr) * LDA
                                             + k0 + b_koff) * 2);
                ldm_x4(b[np], bd);
            }
#pragma unroll
            for (int mt = 0; mt < 2; mt++)
#pragma unroll
                for (int nt = 0; nt < 8; nt++)
                    mma_bf16(acc[mt][nt], a[mt], &b[nt >> 1][(nt & 1) * 2]);
        }
    }

    const float* s_bias = (const float*)(smem + SM_BIAS);
    const float* s_att = (const float*)(smem + SM_ATT);
    const int q = lane & 3, rg = lane >> 2;

#pragma unroll
    for (int mt = 0; mt < 2; mt++) {
#pragma unroll
        for (int hh = 0; hh < 2; hh++) {
            const int r = mrow + mt * 16 + rg + hh * 8;
            const int grow = rowBase + r;
            const bool valid = grow < M;
            float pt0 = 0.f, ps0 = 0.f, pt1 = 0.f, ps1 = 0.f;
#pragma unroll
            for (int nt = 0; nt < 8; nt++) {
                const int col = ncol + nt * 8 + 2 * q;
                float v0 = acc[mt][nt][hh * 2 + 0] + s_bias[col];
                float v1 = acc[mt][nt][hh * 2 + 1] + s_bias[col + 1];
                if (valid)
                    *(float2*)(g_h + (size_t)grow * HC + col) = make_float2(v0, v1);
                const int head = wc * 2 + (nt >> 2);
                const int c0 = col & 31;
                const float at0 = s_att[head * 64 + c0], at1 = s_att[head * 64 + c0 + 1];
                const float as0 = s_att[head * 64 + 32 + c0], as1 = s_att[head * 64 + 33 + c0];
                if (nt < 4) { pt0 += v0 * at0 + v1 * at1; ps0 += v0 * as0 + v1 * as1; }
                else        { pt1 += v0 * at0 + v1 * at1; ps1 += v0 * as0 + v1 * as1; }
            }
#pragma unroll
            for (int o = 1; o <= 2; o <<= 1) {
                pt0 += __shfl_xor_sync(0xffffffffu, pt0, o);
                ps0 += __shfl_xor_sync(0xffffffffu, ps0, o);
                pt1 += __shfl_xor_sync(0xffffffffu, pt1, o);
                ps1 += __shfl_xor_sync(0xffffffffu, ps1, o);
            }
            if (q == 0 && valid) {
                const int h0 = wc * 2;
                g_at[(size_t)grow * HEADS + h0] = pt0;
                g_at[(size_t)grow * HEADS + h0 + 1] = pt1;
                g_as[(size_t)grow * HEADS + h0] = ps0;
                g_as[(size_t)grow * HEADS + h0 + 1] = ps1;
            }
        }
    }
}

// ---------------- E1: decode idx, gather logits, store e, global max ----------------
__global__ __launch_bounds__(256) void edge_pass1(const void* __restrict__ idx, int E) {
    int i = blockIdx.x * blockDim.x + threadIdx.x;
    int is64 = g_is64;
    float m = -3.4e38f;
    if (i < E) {
        int s = ldidx(idx, i, is64);
        int t = ldidx(idx, (long long)E + i, is64);
        g_edges[i] = make_int2(s, t);
        float4 at = __ldg((const float4*)(g_at + (size_t)t * HEADS));
        float4 as = __ldg((const float4*)(g_as + (size_t)s * HEADS));
        float4 e = make_float4(at.x + as.x, at.y + as.y, at.z + as.z, at.w + as.w);
        g_e4[i] = e;
        m = fmaxf(fmaxf(e.x, e.y), fmaxf(e.z, e.w));
    }
    unsigned int u = f2o(m);
#pragma unroll
    for (int o = 16; o; o >>= 1)
        u = max(u, __shfl_down_sync(0xffffffffu, u, o));
    __shared__ unsigned int sm[8];
    int lane = threadIdx.x & 31, warp = threadIdx.x >> 5;
    if (lane == 0) sm[warp] = u;
    __syncthreads();
    if (warp == 0) {
        u = (lane < 8) ? sm[lane] : 0u;
#pragma unroll
        for (int o = 4; o; o >>= 1)
            u = max(u, __shfl_down_sync(0xffffffffu, u, o));
        if (lane == 0) atomicMax(&g_maxbits, u);
    }
}

// ---------------- zero denominators ----------------
__global__ __launch_bounds__(256) void zero_den_kernel(int M) {
    int i = blockIdx.x * blockDim.x + threadIdx.x;
    if (i < M * HEADS) g_den[i] = 0.f;
}

// ---------------- E2: exp weights (in place) + vector-red denominators ----------------
__global__ __launch_bounds__(256) void edge_pass2(int E) {
    int i = blockIdx.x * blockDim.x + threadIdx.x;
    if (i >= E) return;
    float gmax = o2f(g_maxbits);
    float4 e = g_e4[i];
    int t = g_edges[i].y;
    float4 a;
    float d;
    d = e.x - gmax; a.x = __expf(d > 0.f ? d : 0.01f * d);
    d = e.y - gmax; a.y = __expf(d > 0.f ? d : 0.01f * d);
    d = e.z - gmax; a.z = __expf(d > 0.f ? d : 0.01f * d);
    d = e.w - gmax; a.w = __expf(d > 0.f ? d : 0.01f * d);
    g_e4[i] = a;
    red_v4(g_den + (size_t)t * HEADS, a);
}

// ---------------- E3: weighted aggregation, 8 lanes per edge ----------------
__global__ __launch_bounds__(256) void agg_kernel(int E, float* __restrict__ out) {
    int gtid = blockIdx.x * blockDim.x + threadIdx.x;
    int eid = gtid >> 3;
    if (eid >= E) return;
    int lg = gtid & 7;                       // lane-in-group: channel block lg*4
    int2 st = __ldg((const int2*)&g_edges[eid]);
    float4 a = __ldg((const float4*)&g_e4[eid]);
    float4 den = __ldg((const float4*)(g_den + (size_t)st.y * HEADS));
    float w0 = 0.25f * a.x / (den.x + EPS_F);
    float w1 = 0.25f * a.y / (den.y + EPS_F);
    float w2 = 0.25f * a.z / (den.z + EPS_F);
    float w3 = 0.25f * a.w / (den.w + EPS_F);
    const float* hs = g_h + (size_t)st.x * HC + lg * 4;
    float4 h0 = __ldg((const float4*)(hs));
    float4 h1 = __ldg((const float4*)(hs + 32));
    float4 h2 = __ldg((const float4*)(hs + 64));
    float4 h3 = __ldg((const float4*)(hs + 96));
    float4 v;
    v.x = w0 * h0.x + w1 * h1.x + w2 * h2.x + w3 * h3.x;
    v.y = w0 * h0.y + w1 * h1.y + w2 * h2.y + w3 * h3.y;
    v.z = w0 * h0.z + w1 * h1.z + w2 * h2.z + w3 * h3.z;
    v.w = w0 * h0.w + w1 * h1.w + w2 * h2.w + w3 * h3.w;
    red_v4(out + (size_t)st.y * OUT_CH + lg * 4, v);
}

// ---------------- launch ----------------
extern "C" void kernel_launch(void* const* d_in, const int* in_sizes, int n_in,
                              void* d_out, int out_size) {
    const float* X    = (const float*)d_in[0];
    const void*  eidx = d_in[1];
    const float* W    = (const float*)d_in[2];
    const float* bias = (const float*)d_in[3];
    const float* att  = (const float*)d_in[4];
    float* out = (float*)d_out;

    int M = in_sizes[0] / IN_CH;          // nodes
    int E = in_sizes[1] / 2;              // edges

    cudaFuncSetAttribute(gat_gemm_kernel,
                         cudaFuncAttributeMaxDynamicSharedMemorySize, SM_TOTAL);

    int nscan = E < 2048 ? E : 2048;
    init_kernel<<<1, 256>>>(eidx, nscan, M);
    prep_w_kernel<<<32, 256>>>(W);

    cudaMemsetAsync(d_out, 0, (size_t)out_size * sizeof(float));
    zero_den_kernel<<<(M * HEADS + 255) / 256, 256>>>(M);

    gat_gemm_kernel<<<(M + TILE_M - 1) / TILE_M, 256, SM_TOTAL>>>(X, bias, att, M);

    edge_pass1<<<(E + 255) / 256, 256>>>(eidx, E);
    edge_pass2<<<(E + 255) / 256, 256>>>(E);

    long long aggThreads = (long long)E * 8;
    agg_kernel<<<(unsigned)((aggThreads + 255) / 256), 256>>>(E, out);
}

// round 5
// speedup vs baseline: 2.5812x; 1.0873x over previous
#include <cuda_runtime.h>
#include <cuda_bf16.h>
#include <cstdint>

#define N_NODES_C 100000
#define N_EDGES_C 800000
#define HEADS 4
#define OUT_CH 32
#define IN_CH 128
#define HC 128            // HEADS*OUT_CH
#define EPS_F 1e-8f
#define TILE_M 64

// ---------------- device scratch (no allocs allowed) ----------------
__device__ __align__(16) float g_h[(size_t)N_NODES_C * HC];   // projected features [N,128]
__device__ __align__(16) float g_at[N_NODES_C * HEADS];       // alpha_t -> exp factors
__device__ __align__(16) float g_as[N_NODES_C * HEADS];       // alpha_s -> exp factors
__device__ __align__(16) float g_den[N_NODES_C * HEADS];      // softmax denominators
__device__ __align__(16) int2  g_edges[N_EDGES_C];            // decoded (s,t)
__device__ __align__(16) float4 g_e4[N_EDGES_C];              // per-edge softmax numerators
__device__ unsigned int g_maxt, g_maxs;                       // ordered-encoded node maxes
__device__ int g_is64;                                        // edge index dtype flag
__device__ __align__(16) unsigned short g_Whi[HC * 128];      // W bf16 hi, swizzled
__device__ __align__(16) unsigned short g_Wlo[HC * 128];      // W bf16 lo, swizzled

// ordered float <-> uint mapping for atomicMax on floats
__device__ __forceinline__ unsigned int f2o(float f) {
    unsigned int b = __float_as_uint(f);
    return (b & 0x80000000u) ? ~b : (b | 0x80000000u);
}
__device__ __forceinline__ float o2f(unsigned int u) {
    unsigned int b = (u & 0x80000000u) ? (u ^ 0x80000000u) : ~u;
    return __uint_as_float(b);
}
__device__ __forceinline__ int ldidx(const void* p, long long i, int is64) {
    return is64 ? (int)((const long long*)p)[i] : ((const int*)p)[i];
}
__device__ __forceinline__ void red_v4(float* ptr, float4 v) {
    asm volatile("red.global.add.v4.f32 [%0], {%1,%2,%3,%4};"
                 :: "l"(ptr), "f"(v.x), "f"(v.y), "f"(v.z), "f"(v.w) : "memory");
}
__device__ __forceinline__ uint32_t smem_u32(const void* p) {
    uint32_t a;
    asm("{ .reg .u64 t; cvta.to.shared.u64 t, %1; cvt.u32.u64 %0, t; }" : "=r"(a) : "l"(p));
    return a;
}
__device__ __forceinline__ void cp_async16(uint32_t saddr, const void* gaddr) {
    asm volatile("cp.async.cg.shared.global [%0], [%1], 16;" :: "r"(saddr), "l"(gaddr));
}
__device__ __forceinline__ void ldm_x4(uint32_t* r, uint32_t addr) {
    asm volatile("ldmatrix.sync.aligned.m8n8.x4.shared.b16 {%0,%1,%2,%3}, [%4];"
                 : "=r"(r[0]), "=r"(r[1]), "=r"(r[2]), "=r"(r[3]) : "r"(addr));
}
__device__ __forceinline__ void mma_bf16(float* d, const uint32_t* a, const uint32_t* b) {
    asm volatile(
        "mma.sync.aligned.m16n8k16.row.col.f32.bf16.bf16.f32 "
        "{%0,%1,%2,%3}, {%4,%5,%6,%7}, {%8,%9}, {%0,%1,%2,%3};"
        : "+f"(d[0]), "+f"(d[1]), "+f"(d[2]), "+f"(d[3])
        : "r"(a[0]), "r"(a[1]), "r"(a[2]), "r"(a[3]), "r"(b[0]), "r"(b[1]));
}

// XOR swizzle: row stride 256B (128 bf16); flips 16B-chunk index bits with row&7
__device__ __forceinline__ uint32_t swz(int row, int kByte) {
    return (uint32_t)(row * 256 + (kByte ^ ((row & 7) << 4)));
}

// SMEM layout (bytes)
#define SM_BIAS 0
#define SM_ATT  512
#define SM_AHI  1536
#define SM_ALO  (SM_AHI + 16384)
#define SM_BHI  (SM_ALO + 16384)
#define SM_BLO  (SM_BHI + 32768)
#define SM_TOTAL (SM_BLO + 32768)   // 99840

// ---------------- init: dtype detection + max reset ----------------
__global__ void init_kernel(const void* __restrict__ idx, int nscan, int nnodes) {
    __shared__ int bad;
    if (threadIdx.x == 0) bad = 0;
    __syncthreads();
    const long long* p = (const long long*)idx;
    int ok = 1;
    for (int i = threadIdx.x; i < nscan; i += blockDim.x) {
        long long v = p[i];
        if (v < 0 || v >= (long long)nnodes) ok = 0;
    }
    if (!ok) atomicExch(&bad, 1);
    __syncthreads();
    if (threadIdx.x == 0) {
        g_is64 = bad ? 0 : 1;
        g_maxt = 0u;
        g_maxs = 0u;
    }
}

// ---------------- W -> bf16 hi/lo, swizzled [n][k] ----------------
__global__ void prep_w_kernel(const float* __restrict__ W) {
    for (int idx = blockIdx.x * blockDim.x + threadIdx.x; idx < HC * IN_CH;
         idx += blockDim.x * gridDim.x) {
        int n = idx >> 7;
        int k = idx & 127;
        float w = W[idx];
        __nv_bfloat16 hi = __float2bfloat16(w);
        float rem = w - __bfloat162float(hi);
        __nv_bfloat16 lo = __float2bfloat16(rem);
        uint32_t off = swz(n, k * 2) >> 1;
        g_Whi[off] = __bfloat16_as_ushort(hi);
        g_Wlo[off] = __bfloat16_as_ushort(lo);
    }
}

// ---------------- mma.sync GEMM + fused alpha epilogue ----------------
// 64x128 tile per CTA, 2 CTAs/SM; 8 warps in 2x4 (row x col); warp tile 32x32.
__global__ void __launch_bounds__(256, 2)
gat_gemm_kernel(const float* __restrict__ X, const float* __restrict__ bias,
                const float* __restrict__ att, int M) {
    extern __shared__ char smem[];
    const uint32_t sb = smem_u32(smem);
    const int tid = threadIdx.x, lane = tid & 31, wid = tid >> 5;
    const int rowBase = blockIdx.x * TILE_M;

    if (tid < 128) ((float*)(smem + SM_BIAS))[tid] = bias[tid];
    ((float*)(smem + SM_ATT))[tid] = att[tid];

    // async copy of pre-swizzled W hi/lo (32 KB each)
    {
        const char* wh = (const char*)g_Whi;
        const char* wl = (const char*)g_Wlo;
#pragma unroll
        for (int it = 0; it < 8; it++) {
            int g = (tid + it * 256) * 16;
            cp_async16(sb + SM_BHI + g, wh + g);
            cp_async16(sb + SM_BLO + g, wl + g);
        }
        asm volatile("cp.async.commit_group;");
    }
    // A tile: load fp32 X, split into bf16 hi/lo, swizzled
#pragma unroll
    for (int it = 0; it < 8; it++) {
        int g = tid + it * 256;      // 0..2047
        int r = g >> 5;
        int c4 = (g & 31) * 4;
        int grow = rowBase + r;
        float4 v = make_float4(0.f, 0.f, 0.f, 0.f);
        if (grow < M) v = *(const float4*)(X + (size_t)grow * IN_CH + c4);
        __nv_bfloat16 h0 = __float2bfloat16(v.x);
        __nv_bfloat16 h1 = __float2bfloat16(v.y);
        __nv_bfloat16 h2 = __float2bfloat16(v.z);
        __nv_bfloat16 h3 = __float2bfloat16(v.w);
        __nv_bfloat16 l0 = __float2bfloat16(v.x - __bfloat162float(h0));
        __nv_bfloat16 l1 = __float2bfloat16(v.y - __bfloat162float(h1));
        __nv_bfloat16 l2 = __float2bfloat16(v.z - __bfloat162float(h2));
        __nv_bfloat16 l3 = __float2bfloat16(v.w - __bfloat162float(h3));
        uint32_t hiA = ((uint32_t)__bfloat16_as_ushort(h1) << 16) | __bfloat16_as_ushort(h0);
        uint32_t hiB = ((uint32_t)__bfloat16_as_ushort(h3) << 16) | __bfloat16_as_ushort(h2);
        uint32_t loA = ((uint32_t)__bfloat16_as_ushort(l1) << 16) | __bfloat16_as_ushort(l0);
        uint32_t loB = ((uint32_t)__bfloat16_as_ushort(l3) << 16) | __bfloat16_as_ushort(l2);
        uint32_t off = swz(r, c4 * 2);
        *(uint2*)(smem + SM_AHI + off) = make_uint2(hiA, hiB);
        *(uint2*)(smem + SM_ALO + off) = make_uint2(loA, loB);
    }
    asm volatile("cp.async.wait_group 0;" ::: "memory");
    __syncthreads();

    const int wr = wid & 1, wc = wid >> 1;
    const int mrow = wr * 32;      // warp row base (32 rows)
    const int ncol = wc * 32;      // warp col base = head wc

    float acc[2][4][4];
#pragma unroll
    for (int mt = 0; mt < 2; mt++)
#pragma unroll
        for (int nt = 0; nt < 4; nt++)
#pragma unroll
            for (int i = 0; i < 4; i++) acc[mt][nt][i] = 0.f;

    const int a_row = (lane & 15);
    const int a_koff = (lane >> 4) * 8;
    const int b_nr = (lane & 7) + ((lane >> 4) & 1) * 8;
    const int b_koff = ((lane >> 3) & 1) * 8;

#pragma unroll
    for (int p = 0; p < 3; p++) {
        const uint32_t Ab = sb + (p == 2 ? SM_ALO : SM_AHI);
        const uint32_t Bb = sb + (p == 1 ? SM_BLO : SM_BHI);
#pragma unroll
        for (int ks = 0; ks < 8; ks++) {
            const int k0 = ks * 16;
            uint32_t a[2][4];
#pragma unroll
            for (int mt = 0; mt < 2; mt++) {
                int row = mrow + mt * 16 + a_row;
                ldm_x4(a[mt], Ab + swz(row, (k0 + a_koff) * 2));
            }
            uint32_t b[2][4];
#pragma unroll
            for (int np = 0; np < 2; np++) {
                int row = ncol + np * 16 + b_nr;
                ldm_x4(b[np], Bb + swz(row, (k0 + b_koff) * 2));
            }
#pragma unroll
            for (int mt = 0; mt < 2; mt++)
#pragma unroll
                for (int nt = 0; nt < 4; nt++)
                    mma_bf16(acc[mt][nt], a[mt], &b[nt >> 1][(nt & 1) * 2]);
        }
    }

    // epilogue: bias, store g_h, fused alpha dots (head = wc per warp)
    const float* s_bias = (const float*)(smem + SM_BIAS);
    const float* s_att = (const float*)(smem + SM_ATT);
    const int q = lane & 3, rg = lane >> 2;

#pragma unroll
    for (int mt = 0; mt < 2; mt++) {
#pragma unroll
        for (int hh = 0; hh < 2; hh++) {
            const int r = mrow + mt * 16 + hh * 8 + rg;
            const int grow = rowBase + r;
            const bool valid = grow < M;
            float pt = 0.f, ps = 0.f;
#pragma unroll
            for (int nt = 0; nt < 4; nt++) {
                const int c0 = nt * 8 + 2 * q;          // 0..31 within head
                const int col = ncol + c0;
                float v0 = acc[mt][nt][hh * 2 + 0] + s_bias[col];
                float v1 = acc[mt][nt][hh * 2 + 1] + s_bias[col + 1];
                if (valid)
                    *(float2*)(g_h + (size_t)grow * HC + col) = make_float2(v0, v1);
                pt += v0 * s_att[wc * 64 + c0] + v1 * s_att[wc * 64 + c0 + 1];
                ps += v0 * s_att[wc * 64 + 32 + c0] + v1 * s_att[wc * 64 + 33 + c0];
            }
#pragma unroll
            for (int o = 1; o <= 2; o <<= 1) {
                pt += __shfl_xor_sync(0xffffffffu, pt, o);
                ps += __shfl_xor_sync(0xffffffffu, ps, o);
            }
            if (q == 0 && valid) {
                g_at[(size_t)grow * HEADS + wc] = pt;
                g_as[(size_t)grow * HEADS + wc] = ps;
            }
        }
    }
}

// ---------------- node max reduce over g_at / g_as ----------------
__global__ __launch_bounds__(256) void nodemax_kernel(int n) {
    float mt = -3.4e38f, ms = -3.4e38f;
    for (int i = blockIdx.x * blockDim.x + threadIdx.x; i < n; i += blockDim.x * gridDim.x) {
        mt = fmaxf(mt, g_at[i]);
        ms = fmaxf(ms, g_as[i]);
    }
    unsigned int ut = f2o(mt), us = f2o(ms);
#pragma unroll
    for (int o = 16; o; o >>= 1) {
        ut = max(ut, __shfl_down_sync(0xffffffffu, ut, o));
        us = max(us, __shfl_down_sync(0xffffffffu, us, o));
    }
    __shared__ unsigned int smt[8], sms[8];
    int lane = threadIdx.x & 31, warp = threadIdx.x >> 5;
    if (lane == 0) { smt[warp] = ut; sms[warp] = us; }
    __syncthreads();
    if (warp == 0) {
        ut = (lane < 8) ? smt[lane] : 0u;
        us = (lane < 8) ? sms[lane] : 0u;
#pragma unroll
        for (int o = 4; o; o >>= 1) {
            ut = max(ut, __shfl_down_sync(0xffffffffu, ut, o));
            us = max(us, __shfl_down_sync(0xffffffffu, us, o));
        }
        if (lane == 0) {
            atomicMax(&g_maxt, ut);
            atomicMax(&g_maxs, us);
        }
    }
}

// ---------------- per-node exp factors (in place) + zero denominators ----------------
__global__ __launch_bounds__(256) void nodeexp_kernel(int n) {
    int i = blockIdx.x * blockDim.x + threadIdx.x;
    if (i >= n) return;
    float Gt = o2f(g_maxt), Gs = o2f(g_maxs);
    g_at[i] = __expf(0.01f * (g_at[i] - Gt));
    g_as[i] = __expf(0.01f * (g_as[i] - Gs));
    g_den[i] = 0.f;
}

// ---------------- E1: decode, per-edge weights, denominator red ----------------
__global__ __launch_bounds__(256) void edge_pass1(const void* __restrict__ idx, int E) {
    int i = blockIdx.x * blockDim.x + threadIdx.x;
    if (i >= E) return;
    int is64 = g_is64;
    int s = ldidx(idx, i, is64);
    int t = ldidx(idx, (long long)E + i, is64);
    g_edges[i] = make_int2(s, t);
    float4 et = __ldg((const float4*)(g_at + (size_t)t * HEADS));
    float4 es = __ldg((const float4*)(g_as + (size_t)s * HEADS));
    float4 w = make_float4(et.x * es.x, et.y * es.y, et.z * es.z, et.w * es.w);
    g_e4[i] = w;
    red_v4(g_den + (size_t)t * HEADS, w);
}

// ---------------- E3: weighted aggregation, 8 lanes per edge ----------------
__global__ __launch_bounds__(256) void agg_kernel(int E, float* __restrict__ out) {
    int gtid = blockIdx.x * blockDim.x + threadIdx.x;
    int eid = gtid >> 3;
    if (eid >= E) return;
    int lg = gtid & 7;
    int2 st = __ldg((const int2*)&g_edges[eid]);
    float4 a = __ldg((const float4*)&g_e4[eid]);
    float4 den = __ldg((const float4*)(g_den + (size_t)st.y * HEADS));
    float w0 = 0.25f * a.x / (den.x + EPS_F);
    float w1 = 0.25f * a.y / (den.y + EPS_F);
    float w2 = 0.25f * a.z / (den.z + EPS_F);
    float w3 = 0.25f * a.w / (den.w + EPS_F);
    const float* hs = g_h + (size_t)st.x * HC + lg * 4;
    float4 h0 = __ldg((const float4*)(hs));
    float4 h1 = __ldg((const float4*)(hs + 32));
    float4 h2 = __ldg((const float4*)(hs + 64));
    float4 h3 = __ldg((const float4*)(hs + 96));
    float4 v;
    v.x = w0 * h0.x + w1 * h1.x + w2 * h2.x + w3 * h3.x;
    v.y = w0 * h0.y + w1 * h1.y + w2 * h2.y + w3 * h3.y;
    v.z = w0 * h0.z + w1 * h1.z + w2 * h2.z + w3 * h3.z;
    v.w = w0 * h0.w + w1 * h1.w + w2 * h2.w + w3 * h3.w;
    red_v4(out + (size_t)st.y * OUT_CH + lg * 4, v);
}

// ---------------- launch ----------------
extern "C" void kernel_launch(void* const* d_in, const int* in_sizes, int n_in,
                              void* d_out, int out_size) {
    const float* X    = (const float*)d_in[0];
    const void*  eidx = d_in[1];
    const float* W    = (const float*)d_in[2];
    const float* bias = (const float*)d_in[3];
    const float* att  = (const float*)d_in[4];
    float* out = (float*)d_out;

    int M = in_sizes[0] / IN_CH;          // nodes
    int E = in_sizes[1] / 2;              // edges

    cudaFuncSetAttribute(gat_gemm_kernel,
                         cudaFuncAttributeMaxDynamicSharedMemorySize, SM_TOTAL);

    int nscan = E < 2048 ? E : 2048;
    init_kernel<<<1, 256>>>(eidx, nscan, M);
    prep_w_kernel<<<32, 256>>>(W);

    cudaMemsetAsync(d_out, 0, (size_t)out_size * sizeof(float));

    gat_gemm_kernel<<<(M + TILE_M - 1) / TILE_M, 256, SM_TOTAL>>>(X, bias, att, M);

    nodemax_kernel<<<400, 256>>>(M * HEADS);
    nodeexp_kernel<<<(M * HEADS + 255) / 256, 256>>>(M * HEADS);

    edge_pass1<<<(E + 255) / 256, 256>>>(eidx, E);

    long long aggThreads = (long long)E * 8;
    agg_kernel<<<(unsigned)((aggThreads + 255) / 256), 256>>>(E, out);
}

// round 6
// speedup vs baseline: 2.7675x; 1.0722x over previous
#include <cuda_runtime.h>
#include <cuda_bf16.h>
#include <cstdint>

#define N_NODES_C 100000
#define N_EDGES_C 800000
#define HEADS 4
#define OUT_CH 32
#define IN_CH 128
#define HC 128            // HEADS*OUT_CH
#define EPS_F 1e-8f
#define TILE_M 64

// ---------------- device scratch (no allocs allowed) ----------------
__device__ __align__(16) float g_h[(size_t)N_NODES_C * HC];   // projected features [N,128]
__device__ __align__(16) float g_as[N_NODES_C * HEADS];       // alpha_s -> exp factors
__device__ __align__(16) float g_den[N_NODES_C * HEADS];      // softmax denominators
__device__ __align__(16) int2  g_edges[N_EDGES_C];            // decoded (s,t)
__device__ unsigned int g_maxs;                               // ordered-encoded max of as
__device__ int g_is64;                                        // edge index dtype flag
__device__ __align__(16) unsigned short g_Whi[HC * 128];      // W bf16 hi, swizzled
__device__ __align__(16) unsigned short g_Wlo[HC * 128];      // W bf16 lo, swizzled

// ordered float <-> uint mapping for atomicMax on floats
__device__ __forceinline__ unsigned int f2o(float f) {
    unsigned int b = __float_as_uint(f);
    return (b & 0x80000000u) ? ~b : (b | 0x80000000u);
}
__device__ __forceinline__ float o2f(unsigned int u) {
    unsigned int b = (u & 0x80000000u) ? (u ^ 0x80000000u) : ~u;
    return __uint_as_float(b);
}
__device__ __forceinline__ int ldidx(const void* p, long long i, int is64) {
    return is64 ? (int)((const long long*)p)[i] : ((const int*)p)[i];
}
__device__ __forceinline__ void red_v4(float* ptr, float4 v) {
    asm volatile("red.global.add.v4.f32 [%0], {%1,%2,%3,%4};"
                 :: "l"(ptr), "f"(v.x), "f"(v.y), "f"(v.z), "f"(v.w) : "memory");
}
__device__ __forceinline__ uint32_t smem_u32(const void* p) {
    uint32_t a;
    asm("{ .reg .u64 t; cvta.to.shared.u64 t, %1; cvt.u32.u64 %0, t; }" : "=r"(a) : "l"(p));
    return a;
}
__device__ __forceinline__ void cp_async16(uint32_t saddr, const void* gaddr) {
    asm volatile("cp.async.cg.shared.global [%0], [%1], 16;" :: "r"(saddr), "l"(gaddr));
}
__device__ __forceinline__ void ldm_x4(uint32_t* r, uint32_t addr) {
    asm volatile("ldmatrix.sync.aligned.m8n8.x4.shared.b16 {%0,%1,%2,%3}, [%4];"
                 : "=r"(r[0]), "=r"(r[1]), "=r"(r[2]), "=r"(r[3]) : "r"(addr));
}
__device__ __forceinline__ void mma_bf16(float* d, const uint32_t* a, const uint32_t* b) {
    asm volatile(
        "mma.sync.aligned.m16n8k16.row.col.f32.bf16.bf16.f32 "
        "{%0,%1,%2,%3}, {%4,%5,%6,%7}, {%8,%9}, {%0,%1,%2,%3};"
        : "+f"(d[0]), "+f"(d[1]), "+f"(d[2]), "+f"(d[3])
        : "r"(a[0]), "r"(a[1]), "r"(a[2]), "r"(a[3]), "r"(b[0]), "r"(b[1]));
}

// XOR swizzle: row stride 256B (128 bf16); flips 16B-chunk index bits with row&7
__device__ __forceinline__ uint32_t swz(int row, int kByte) {
    return (uint32_t)(row * 256 + (kByte ^ ((row & 7) << 4)));
}

// SMEM layout (bytes)
#define SM_BIAS 0
#define SM_ATT  512
#define SM_RED  1024
#define SM_AHI  1536
#define SM_ALO  (SM_AHI + 16384)
#define SM_BHI  (SM_ALO + 16384)
#define SM_BLO  (SM_BHI + 32768)
#define SM_TOTAL (SM_BLO + 32768)   // 99840

// ---------------- init: dtype detection + max reset ----------------
__global__ void init_kernel(const void* __restrict__ idx, int nscan, int nnodes) {
    __shared__ int bad;
    if (threadIdx.x == 0) bad = 0;
    __syncthreads();
    const long long* p = (const long long*)idx;
    int ok = 1;
    for (int i = threadIdx.x; i < nscan; i += blockDim.x) {
        long long v = p[i];
        if (v < 0 || v >= (long long)nnodes) ok = 0;
    }
    if (!ok) atomicExch(&bad, 1);
    __syncthreads();
    if (threadIdx.x == 0) {
        g_is64 = bad ? 0 : 1;
        g_maxs = 0u;
    }
}

// ---------------- W -> bf16 hi/lo, swizzled [n][k] ----------------
__global__ void prep_w_kernel(const float* __restrict__ W) {
    for (int idx = blockIdx.x * blockDim.x + threadIdx.x; idx < HC * IN_CH;
         idx += blockDim.x * gridDim.x) {
        int n = idx >> 7;
        int k = idx & 127;
        float w = W[idx];
        __nv_bfloat16 hi = __float2bfloat16(w);
        float rem = w - __bfloat162float(hi);
        __nv_bfloat16 lo = __float2bfloat16(rem);
        uint32_t off = swz(n, k * 2) >> 1;
        g_Whi[off] = __bfloat16_as_ushort(hi);
        g_Wlo[off] = __bfloat16_as_ushort(lo);
    }
}

// ---------------- mma.sync GEMM + fused alpha_s epilogue + CTA max ----------------
// 64x128 tile per CTA, 2 CTAs/SM; 8 warps in 2x4 (row x col); warp tile 32x32.
__global__ void __launch_bounds__(256, 2)
gat_gemm_kernel(const float* __restrict__ X, const float* __restrict__ bias,
                const float* __restrict__ att, int M) {
    extern __shared__ char smem[];
    const uint32_t sb = smem_u32(smem);
    const int tid = threadIdx.x, lane = tid & 31, wid = tid >> 5;
    const int rowBase = blockIdx.x * TILE_M;

    if (tid < 128) ((float*)(smem + SM_BIAS))[tid] = bias[tid];
    ((float*)(smem + SM_ATT))[tid] = att[tid];

    // async copy of pre-swizzled W hi/lo (32 KB each)
    {
        const char* wh = (const char*)g_Whi;
        const char* wl = (const char*)g_Wlo;
#pragma unroll
        for (int it = 0; it < 8; it++) {
            int g = (tid + it * 256) * 16;
            cp_async16(sb + SM_BHI + g, wh + g);
            cp_async16(sb + SM_BLO + g, wl + g);
        }
        asm volatile("cp.async.commit_group;");
    }
    // A tile: load fp32 X, split into bf16 hi/lo, swizzled
#pragma unroll
    for (int it = 0; it < 8; it++) {
        int g = tid + it * 256;      // 0..2047
        int r = g >> 5;
        int c4 = (g & 31) * 4;
        int grow = rowBase + r;
        float4 v = make_float4(0.f, 0.f, 0.f, 0.f);
        if (grow < M) v = *(const float4*)(X + (size_t)grow * IN_CH + c4);
        __nv_bfloat16 h0 = __float2bfloat16(v.x);
        __nv_bfloat16 h1 = __float2bfloat16(v.y);
        __nv_bfloat16 h2 = __float2bfloat16(v.z);
        __nv_bfloat16 h3 = __float2bfloat16(v.w);
        __nv_bfloat16 l0 = __float2bfloat16(v.x - __bfloat162float(h0));
        __nv_bfloat16 l1 = __float2bfloat16(v.y - __bfloat162float(h1));
        __nv_bfloat16 l2 = __float2bfloat16(v.z - __bfloat162float(h2));
        __nv_bfloat16 l3 = __float2bfloat16(v.w - __bfloat162float(h3));
        uint32_t hiA = ((uint32_t)__bfloat16_as_ushort(h1) << 16) | __bfloat16_as_ushort(h0);
        uint32_t hiB = ((uint32_t)__bfloat16_as_ushort(h3) << 16) | __bfloat16_as_ushort(h2);
        uint32_t loA = ((uint32_t)__bfloat16_as_ushort(l1) << 16) | __bfloat16_as_ushort(l0);
        uint32_t loB = ((uint32_t)__bfloat16_as_ushort(l3) << 16) | __bfloat16_as_ushort(l2);
        uint32_t off = swz(r, c4 * 2);
        *(uint2*)(smem + SM_AHI + off) = make_uint2(hiA, hiB);
        *(uint2*)(smem + SM_ALO + off) = make_uint2(loA, loB);
    }
    asm volatile("cp.async.wait_group 0;" ::: "memory");
    __syncthreads();

    const int wr = wid & 1, wc = wid >> 1;
    const int mrow = wr * 32;      // warp row base (32 rows)
    const int ncol = wc * 32;      // warp col base = head wc

    float acc[2][4][4];
#pragma unroll
    for (int mt = 0; mt < 2; mt++)
#pragma unroll
        for (int nt = 0; nt < 4; nt++)
#pragma unroll
            for (int i = 0; i < 4; i++) acc[mt][nt][i] = 0.f;

    const int a_row = (lane & 15);
    const int a_koff = (lane >> 4) * 8;
    const int b_nr = (lane & 7) + ((lane >> 4) & 1) * 8;
    const int b_koff = ((lane >> 3) & 1) * 8;

#pragma unroll
    for (int p = 0; p < 3; p++) {
        const uint32_t Ab = sb + (p == 2 ? SM_ALO : SM_AHI);
        const uint32_t Bb = sb + (p == 1 ? SM_BLO : SM_BHI);
#pragma unroll
        for (int ks = 0; ks < 8; ks++) {
            const int k0 = ks * 16;
            uint32_t a[2][4];
#pragma unroll
            for (int mt = 0; mt < 2; mt++) {
                int row = mrow + mt * 16 + a_row;
                ldm_x4(a[mt], Ab + swz(row, (k0 + a_koff) * 2));
            }
            uint32_t b[2][4];
#pragma unroll
            for (int np = 0; np < 2; np++) {
                int row = ncol + np * 16 + b_nr;
                ldm_x4(b[np], Bb + swz(row, (k0 + b_koff) * 2));
            }
#pragma unroll
            for (int mt = 0; mt < 2; mt++)
#pragma unroll
                for (int nt = 0; nt < 4; nt++)
                    mma_bf16(acc[mt][nt], a[mt], &b[nt >> 1][(nt & 1) * 2]);
        }
    }

    // epilogue: bias, store g_h, fused alpha_s dot (head = wc per warp), CTA max
    const float* s_bias = (const float*)(smem + SM_BIAS);
    const float* s_att = (const float*)(smem + SM_ATT);
    const int q = lane & 3, rg = lane >> 2;
    float lmax = -3.4e38f;

#pragma unroll
    for (int mt = 0; mt < 2; mt++) {
#pragma unroll
        for (int hh = 0; hh < 2; hh++) {
            const int r = mrow + mt * 16 + hh * 8 + rg;
            const int grow = rowBase + r;
            const bool valid = grow < M;
            float ps = 0.f;
#pragma unroll
            for (int nt = 0; nt < 4; nt++) {
                const int c0 = nt * 8 + 2 * q;          // 0..31 within head
                const int col = ncol + c0;
                float v0 = acc[mt][nt][hh * 2 + 0] + s_bias[col];
                float v1 = acc[mt][nt][hh * 2 + 1] + s_bias[col + 1];
                if (valid)
                    *(float2*)(g_h + (size_t)grow * HC + col) = make_float2(v0, v1);
                ps += v0 * s_att[wc * 64 + 32 + c0] + v1 * s_att[wc * 64 + 33 + c0];
            }
#pragma unroll
            for (int o = 1; o <= 2; o <<= 1)
                ps += __shfl_xor_sync(0xffffffffu, ps, o);
            if (valid) {
                lmax = fmaxf(lmax, ps);
                if (q == 0) g_as[(size_t)grow * HEADS + wc] = ps;
            }
        }
    }
    // CTA-wide max of alpha_s, one atomicMax per CTA
    unsigned int u = f2o(lmax);
#pragma unroll
    for (int o = 16; o; o >>= 1)
        u = max(u, __shfl_down_sync(0xffffffffu, u, o));
    unsigned int* sred = (unsigned int*)(smem + SM_RED);
    if (lane == 0) sred[wid] = u;
    __syncthreads();
    if (wid == 0) {
        u = (lane < 8) ? sred[lane] : 0u;
#pragma unroll
        for (int o = 4; o; o >>= 1)
            u = max(u, __shfl_down_sync(0xffffffffu, u, o));
        if (lane == 0) atomicMax(&g_maxs, u);
    }
}

// ---------------- per-node exp factors (in place) ----------------
__global__ __launch_bounds__(256) void nodeexp_kernel(int n) {
    int i = blockIdx.x * blockDim.x + threadIdx.x;
    if (i >= n) return;
    float Gs = o2f(g_maxs);
    g_as[i] = __expf(0.01f * (g_as[i] - Gs));
}

// ---------------- E1: decode, denominator red ----------------
__global__ __launch_bounds__(256) void edge_pass1(const void* __restrict__ idx, int E) {
    int i = blockIdx.x * blockDim.x + threadIdx.x;
    if (i >= E) return;
    int is64 = g_is64;
    int s = ldidx(idx, i, is64);
    int t = ldidx(idx, (long long)E + i, is64);
    g_edges[i] = make_int2(s, t);
    float4 w = __ldg((const float4*)(g_as + (size_t)s * HEADS));
    red_v4(g_den + (size_t)t * HEADS, w);
}

// ---------------- E3: weighted aggregation, 8 lanes per edge ----------------
__global__ __launch_bounds__(256) void agg_kernel(int E, float* __restrict__ out) {
    int gtid = blockIdx.x * blockDim.x + threadIdx.x;
    int eid = gtid >> 3;
    if (eid >= E) return;
    int lg = gtid & 7;
    int2 st = __ldg((const int2*)&g_edges[eid]);
    float4 a = __ldg((const float4*)(g_as + (size_t)st.x * HEADS));
    float4 den = __ldg((const float4*)(g_den + (size_t)st.y * HEADS));
    float w0 = 0.25f * a.x / (den.x + EPS_F);
    float w1 = 0.25f * a.y / (den.y + EPS_F);
    float w2 = 0.25f * a.z / (den.z + EPS_F);
    float w3 = 0.25f * a.w / (den.w + EPS_F);
    const float* hs = g_h + (size_t)st.x * HC + lg * 4;
    float4 h0 = __ldg((const float4*)(hs));
    float4 h1 = __ldg((const float4*)(hs + 32));
    float4 h2 = __ldg((const float4*)(hs + 64));
    float4 h3 = __ldg((const float4*)(hs + 96));
    float4 v;
    v.x = w0 * h0.x + w1 * h1.x + w2 * h2.x + w3 * h3.x;
    v.y = w0 * h0.y + w1 * h1.y + w2 * h2.y + w3 * h3.y;
    v.z = w0 * h0.z + w1 * h1.z + w2 * h2.z + w3 * h3.z;
    v.w = w0 * h0.w + w1 * h1.w + w2 * h2.w + w3 * h3.w;
    red_v4(out + (size_t)st.y * OUT_CH + lg * 4, v);
}

// ---------------- launch ----------------
extern "C" void kernel_launch(void* const* d_in, const int* in_sizes, int n_in,
                              void* d_out, int out_size) {
    const float* X    = (const float*)d_in[0];
    const void*  eidx = d_in[1];
    const float* W    = (const float*)d_in[2];
    const float* bias = (const float*)d_in[3];
    const float* att  = (const float*)d_in[4];
    float* out = (float*)d_out;

    int M = in_sizes[0] / IN_CH;          // nodes
    int E = in_sizes[1] / 2;              // edges

    cudaFuncSetAttribute(gat_gemm_kernel,
                         cudaFuncAttributeMaxDynamicSharedMemorySize, SM_TOTAL);

    int nscan = E < 2048 ? E : 2048;
    init_kernel<<<1, 256>>>(eidx, nscan, M);
    prep_w_kernel<<<32, 256>>>(W);

    cudaMemsetAsync(d_out, 0, (size_t)out_size * sizeof(float));
    void* denPtr = nullptr;
    cudaGetSymbolAddress(&denPtr, g_den);
    cudaMemsetAsync(denPtr, 0, (size_t)M * HEADS * sizeof(float));

    gat_gemm_kernel<<<(M + TILE_M - 1) / TILE_M, 256, SM_TOTAL>>>(X, bias, att, M);

    nodeexp_kernel<<<(M * HEADS + 255) / 256, 256>>>(M * HEADS);

    edge_pass1<<<(E + 255) / 256, 256>>>(eidx, E);

    long long aggThreads = (long long)E * 8;
    agg_kernel<<<(unsigned)((aggThreads + 255) / 256), 256>>>(E, out);
}